// round 1
// baseline (speedup 1.0000x reference)
#include <cuda_runtime.h>
#include <cuda_bf16.h>

// Problem shape (fixed by the reference): B=8, L=4000, D=512, WINDOW=5.
// Key identity: the cyclic shift by feature index and the unshift cancel.
// The op reduces to: for each (b, feature i), sort consecutive 5-row windows
// whose phase is (i mod 5), circular over L. Pure memory-bound reshuffle.

#define LROWS 4000
#define DCOLS 512
#define BATCH 8
#define TROWS 40               // output rows per tile (multiple of 5)
#define SROWS (TROWS + 9)      // 49 smem rows: [P-4, P+44]
#define NTHREADS 512
#define SMEM_BYTES (SROWS * DCOLS * 4)

// compare-exchange
#define CE(x, y) { float _lo = fminf(x, y); float _hi = fmaxf(x, y); x = _lo; y = _hi; }

__global__ __launch_bounds__(NTHREADS, 2)
void swd_sortwin_kernel(const float* __restrict__ v, float* __restrict__ out) {
    extern __shared__ float sm[];   // [SROWS][DCOLS]

    const int tx   = threadIdx.x;        // == column i (0..511)
    const int tile = blockIdx.x;         // 0..99
    const int b    = blockIdx.y;         // 0..7
    const int P    = tile * TROWS;       // first output row of this tile (mult of 5)

    const float* __restrict__ vb = v   + (size_t)b * LROWS * DCOLS;
    float*       __restrict__ ob = out + (size_t)b * LROWS * DCOLS;

    // ---- Phase 1: cooperative coalesced fill of rows [P-4, P+45) (circular) ----
    #pragma unroll
    for (int j = 0; j < SROWS; j++) {
        int gr = P - 4 + j;
        if (gr < 0)           gr += LROWS;
        else if (gr >= LROWS) gr -= LROWS;
        sm[j * DCOLS + tx] = vb[(size_t)gr * DCOLS + tx];
    }
    __syncthreads();

    // ---- Phase 2: per-column window sorts (column-private: no further syncs) ----
    // Windows for column residue r start at global row b_r = P-4 + ((r+4)%5),
    // i.e., smem row o, o+5, ..., o+40  (9 windows cover all outputs in [P,P+40)).
    const int r = tx % 5;
    const int o = (r + 4) % 5;

    #pragma unroll
    for (int m = 0; m < 9; m++) {
        int base = (o + 5 * m) * DCOLS + tx;
        float a0 = sm[base];
        float a1 = sm[base + 1 * DCOLS];
        float a2 = sm[base + 2 * DCOLS];
        float a3 = sm[base + 3 * DCOLS];
        float a4 = sm[base + 4 * DCOLS];
        // optimal 5-element sorting network (9 comparators)
        CE(a0, a1); CE(a3, a4); CE(a2, a4);
        CE(a2, a3); CE(a0, a3); CE(a0, a2);
        CE(a1, a4); CE(a1, a3); CE(a1, a2);
        sm[base]             = a0;
        sm[base + 1 * DCOLS] = a1;
        sm[base + 2 * DCOLS] = a2;
        sm[base + 3 * DCOLS] = a3;
        sm[base + 4 * DCOLS] = a4;
    }

    // ---- Phase 3: coalesced flush of smem rows [4, 44) -> out rows [P, P+40) ----
    // (reads are this thread's own column, written above by this thread)
    #pragma unroll
    for (int d = 0; d < TROWS; d++) {
        ob[(size_t)(P + d) * DCOLS + tx] = sm[(4 + d) * DCOLS + tx];
    }
}

extern "C" void kernel_launch(void* const* d_in, const int* in_sizes, int n_in,
                              void* d_out, int out_size) {
    // inputs: q (unused), k (unused), v
    const float* v  = (const float*)d_in[2];
    float* out      = (float*)d_out;

    cudaFuncSetAttribute(swd_sortwin_kernel,
                         cudaFuncAttributeMaxDynamicSharedMemorySize, SMEM_BYTES);

    dim3 grid(LROWS / TROWS, BATCH);   // 100 x 8 = 800 blocks
    swd_sortwin_kernel<<<grid, NTHREADS, SMEM_BYTES>>>(v, out);
}

// round 2
// speedup vs baseline: 1.2013x; 1.2013x over previous
#include <cuda_runtime.h>
#include <cuda_bf16.h>

// B=8, L=4000, D=512, WINDOW=5.
// Identity: per-feature cyclic shift and unshift cancel; the op is
// "sort consecutive 5-row windows per column, window phase = col%5, circular".
//
// R2: float4 global+smem transfers, TROWS=20 tile (58KB smem) -> 3 CTAs/SM,
// __launch_bounds__ forces regs<=42 so occupancy is smem-, not RF-, limited.

#define LROWS 4000
#define DCOLS 512
#define DVEC  (DCOLS / 4)          // 128 float4 per row
#define BATCH 8
#define TROWS 20                   // output rows per tile (multiple of 5)
#define SROWS (TROWS + 9)          // 29 smem rows: [P-4, P+25)
#define NTHREADS 512
#define SMEM_BYTES (SROWS * DCOLS * 4)

#define CE(x, y) { float _lo = fminf(x, y); float _hi = fmaxf(x, y); x = _lo; y = _hi; }

__global__ __launch_bounds__(NTHREADS, 3)
void swd_sortwin_kernel(const float4* __restrict__ v, float4* __restrict__ out) {
    extern __shared__ float sm[];            // [SROWS][DCOLS]
    float4* sm4 = (float4*)sm;               // [SROWS][DVEC]

    const int tx   = threadIdx.x;            // 0..511
    const int tile = blockIdx.x;             // 0..199
    const int b    = blockIdx.y;             // 0..7
    const int P    = tile * TROWS;           // first output row (multiple of 5)

    const float4* __restrict__ vb = v   + (size_t)b * LROWS * DVEC;
    float4*       __restrict__ ob = out + (size_t)b * LROWS * DVEC;

    // ---- Phase 1: vectorized coalesced fill of rows [P-4, P+25) (circular) ----
    const int c4 = tx & (DVEC - 1);          // float4 column 0..127
    const int rw = tx >> 7;                  // row slot 0..3
    #pragma unroll
    for (int jj = 0; jj < 8; jj++) {
        int j = jj * 4 + rw;                 // 0..31, need 0..28
        if (j < SROWS) {
            int gr = P - 4 + j;
            if (gr < 0)           gr += LROWS;
            else if (gr >= LROWS) gr -= LROWS;
            sm4[j * DVEC + c4] = vb[(size_t)gr * DVEC + c4];
        }
    }
    __syncthreads();

    // ---- Phase 2: per-column 5-element window sorts (9-comparator network) ----
    // Column residue r = tx%5; windows start at smem row o = (r+4)%5, o+5, ..., o+20.
    // Bank-conflict free: bank = tx%32 (row stride 512 == 0 mod 32).
    {
        const int r = tx % 5;
        const int o = (r + 4) % 5;
        #pragma unroll
        for (int m = 0; m < 5; m++) {
            int base = (o + 5 * m) * DCOLS + tx;
            float a0 = sm[base];
            float a1 = sm[base + 1 * DCOLS];
            float a2 = sm[base + 2 * DCOLS];
            float a3 = sm[base + 3 * DCOLS];
            float a4 = sm[base + 4 * DCOLS];
            CE(a0, a1); CE(a3, a4); CE(a2, a4);
            CE(a2, a3); CE(a0, a3); CE(a0, a2);
            CE(a1, a4); CE(a1, a3); CE(a1, a2);
            sm[base]             = a0;
            sm[base + 1 * DCOLS] = a1;
            sm[base + 2 * DCOLS] = a2;
            sm[base + 3 * DCOLS] = a3;
            sm[base + 4 * DCOLS] = a4;
        }
    }
    __syncthreads();

    // ---- Phase 3: vectorized flush of smem rows [4, 24) -> out rows [P, P+20) ----
    #pragma unroll
    for (int dd = 0; dd < TROWS / 4; dd++) { // 5 iterations
        int d = dd * 4 + rw;                 // 0..19
        ob[(size_t)(P + d) * DVEC + c4] = sm4[(4 + d) * DVEC + c4];
    }
}

extern "C" void kernel_launch(void* const* d_in, const int* in_sizes, int n_in,
                              void* d_out, int out_size) {
    const float4* v = (const float4*)d_in[2];   // inputs: q (unused), k (unused), v
    float4* out     = (float4*)d_out;

    cudaFuncSetAttribute(swd_sortwin_kernel,
                         cudaFuncAttributeMaxDynamicSharedMemorySize, SMEM_BYTES);

    dim3 grid(LROWS / TROWS, BATCH);            // 200 x 8 = 1600 blocks
    swd_sortwin_kernel<<<grid, NTHREADS, SMEM_BYTES>>>(v, out);
}

// round 3
// speedup vs baseline: 1.2026x; 1.0011x over previous
#include <cuda_runtime.h>
#include <cuda_bf16.h>

// B=8, L=4000, D=512, WINDOW=5.
// Identity: per-feature cyclic shift and unshift cancel; the op is
// "sort consecutive 5-row windows per column, window phase = col%5, circular".
//
// R3: TROWS=10 tile (38.9KB smem) -> 4 CTAs/SM = 2048 threads = 100% occupancy.
// Halo re-reads are L2 hits (input 65.5MB < 126MB L2), so DRAM traffic unchanged.

#define LROWS 4000
#define DCOLS 512
#define DVEC  (DCOLS / 4)          // 128 float4 per row
#define BATCH 8
#define TROWS 10                   // output rows per tile (multiple of 5)
#define SROWS (TROWS + 9)          // 19 smem rows: [P-4, P+15)
#define NTHREADS 512
#define SMEM_BYTES (SROWS * DCOLS * 4)   // 38912 B

#define CE(x, y) { float _lo = fminf(x, y); float _hi = fmaxf(x, y); x = _lo; y = _hi; }

__global__ __launch_bounds__(NTHREADS, 4)
void swd_sortwin_kernel(const float4* __restrict__ v, float4* __restrict__ out) {
    extern __shared__ float sm[];            // [SROWS][DCOLS]
    float4* sm4 = (float4*)sm;               // [SROWS][DVEC]

    const int tx   = threadIdx.x;            // 0..511
    const int tile = blockIdx.x;             // 0..399
    const int b    = blockIdx.y;             // 0..7
    const int P    = tile * TROWS;           // first output row (multiple of 5)

    const float4* __restrict__ vb = v   + (size_t)b * LROWS * DVEC;
    float4*       __restrict__ ob = out + (size_t)b * LROWS * DVEC;

    // ---- Phase 1: vectorized coalesced fill of rows [P-4, P+15) (circular) ----
    // 19 rows * 128 float4 = 2432 vector elements, strided by 512 threads.
    #pragma unroll
    for (int k = 0; k < 5; k++) {
        int idx = tx + k * NTHREADS;
        if (idx < SROWS * DVEC) {
            int j  = idx >> 7;               // smem row 0..18
            int c4 = idx & (DVEC - 1);
            int gr = P - 4 + j;
            if (gr < 0)           gr += LROWS;
            else if (gr >= LROWS) gr -= LROWS;
            sm4[j * DVEC + c4] = vb[(size_t)gr * DVEC + c4];
        }
    }
    __syncthreads();

    // ---- Phase 2: per-column 5-element window sorts (9-comparator network) ----
    // Column residue r = tx%5; windows start at smem rows o, o+5, o+10 where
    // o=(r+4)%5. These cover all output rows [4,14). Bank-conflict free
    // (row stride 512 == 0 mod 32). Column-private: no races.
    {
        const int r = tx % 5;
        const int o = (r + 4) % 5;
        #pragma unroll
        for (int m = 0; m < 3; m++) {
            int base = (o + 5 * m) * DCOLS + tx;
            float a0 = sm[base];
            float a1 = sm[base + 1 * DCOLS];
            float a2 = sm[base + 2 * DCOLS];
            float a3 = sm[base + 3 * DCOLS];
            float a4 = sm[base + 4 * DCOLS];
            CE(a0, a1); CE(a3, a4); CE(a2, a4);
            CE(a2, a3); CE(a0, a3); CE(a0, a2);
            CE(a1, a4); CE(a1, a3); CE(a1, a2);
            sm[base]             = a0;
            sm[base + 1 * DCOLS] = a1;
            sm[base + 2 * DCOLS] = a2;
            sm[base + 3 * DCOLS] = a3;
            sm[base + 4 * DCOLS] = a4;
        }
    }
    __syncthreads();

    // ---- Phase 3: vectorized flush of smem rows [4, 14) -> out rows [P, P+10) ----
    // 10 rows * 128 float4 = 1280 vector elements.
    #pragma unroll
    for (int k = 0; k < 3; k++) {
        int idx = tx + k * NTHREADS;
        if (idx < TROWS * DVEC) {
            int d  = idx >> 7;               // 0..9
            int c4 = idx & (DVEC - 1);
            ob[(size_t)(P + d) * DVEC + c4] = sm4[(4 + d) * DVEC + c4];
        }
    }
}

extern "C" void kernel_launch(void* const* d_in, const int* in_sizes, int n_in,
                              void* d_out, int out_size) {
    const float4* v = (const float4*)d_in[2];   // inputs: q (unused), k (unused), v
    float4* out     = (float4*)d_out;

    cudaFuncSetAttribute(swd_sortwin_kernel,
                         cudaFuncAttributeMaxDynamicSharedMemorySize, SMEM_BYTES);

    dim3 grid(LROWS / TROWS, BATCH);            // 400 x 8 = 3200 blocks
    swd_sortwin_kernel<<<grid, NTHREADS, SMEM_BYTES>>>(v, out);
}

// round 5
// speedup vs baseline: 1.3463x; 1.1195x over previous
#include <cuda_runtime.h>
#include <cuda_bf16.h>

// B=8, L=4000, D=512, WINDOW=5.
// Identity: shift/unshift cancel -> per column c, sort consecutive 5-row
// windows whose start rows are ≡ c (mod 5), circular over L.
//
// R5: register-resident, smem-free (R4 + up-shift bounds fix). Warp = 32
// consecutive columns x 20 output rows. Lane loads 29 consecutive rows of its
// column (coalesced), barrel-shifts the frame down by per-lane phase o, sorts
// 5 windows at static offsets, barrel-shifts back up, stores coalesced.

#define LROWS 4000
#define DCOLS 512
#define TROWS 20
#define NREG  (TROWS + 9)      // 29
#define NTHREADS 256

#define CE(x, y) { float _lo = fminf(x, y); float _hi = fmaxf(x, y); x = _lo; y = _hi; }

__global__ __launch_bounds__(NTHREADS, 5)
void swd_reg_kernel(const float* __restrict__ v, float* __restrict__ out) {
    const int lane   = threadIdx.x & 31;
    const int warpid = threadIdx.x >> 5;          // 0..7
    const int rt     = blockIdx.x >> 1;           // row tile 0..199
    const int half   = blockIdx.x & 1;            // 0..1
    const int b      = blockIdx.y;                // batch 0..7
    const int cg     = half * 8 + warpid;         // column group 0..15
    const int c      = cg * 32 + lane;            // column 0..511
    const int P      = rt * TROWS;                // first output row

    float a[NREG];

    // ---- Load rows [P-4, P+25) of column c, coalesced across the warp ----
    if (P >= 4 && P + NREG - 4 <= LROWS) {
        const float* __restrict__ vp =
            v + ((size_t)b * LROWS + (P - 4)) * DCOLS + c;
        #pragma unroll
        for (int j = 0; j < NREG; j++) a[j] = vp[j * DCOLS];
    } else {
        const float* __restrict__ vb = v + (size_t)b * LROWS * DCOLS + c;
        #pragma unroll
        for (int j = 0; j < NREG; j++) {
            int gr = P - 4 + j;
            if (gr < 0)           gr += LROWS;
            else if (gr >= LROWS) gr -= LROWS;
            a[j] = vb[(size_t)gr * DCOLS];
        }
    }

    // ---- Phase: first window start in frame is local index o=(c+4)%5 ----
    const int o  = (c + 4) % 5;
    const bool o1 = (o & 1) != 0;
    const bool o2 = (o & 2) != 0;
    const bool o4 = (o & 4) != 0;

    // ---- Barrel shift DOWN by o: a[j] <- orig[j+o], valid for j=0..24 ----
    // ascending, reads ahead of writes; bounds keep every needed read valid.
    #pragma unroll
    for (int j = 0; j < NREG - 1; j++) a[j] = o1 ? a[j + 1] : a[j];
    #pragma unroll
    for (int j = 0; j < NREG - 2; j++) a[j] = o2 ? a[j + 2] : a[j];
    #pragma unroll
    for (int j = 0; j < NREG - 4; j++) a[j] = o4 ? a[j + 4] : a[j];

    // ---- Sort 5 windows at static offsets 0,5,10,15,20 (9-comparator net) ----
    #pragma unroll
    for (int m = 0; m < 5; m++) {
        float a0 = a[5*m+0], a1 = a[5*m+1], a2 = a[5*m+2],
              a3 = a[5*m+3], a4 = a[5*m+4];
        CE(a0, a1); CE(a3, a4); CE(a2, a4);
        CE(a2, a3); CE(a0, a3); CE(a0, a2);
        CE(a1, a4); CE(a1, a3); CE(a1, a2);
        a[5*m+0] = a0; a[5*m+1] = a1; a[5*m+2] = a2;
        a[5*m+3] = a3; a[5*m+4] = a4;
    }

    // ---- Barrel shift UP by o: a[i] <- sorted[i-o], needed for i=4..23 ----
    // Descending; each stage's lower bound = its shift amount so the NEXT
    // stage's reads below i=4 are also shifted (this was the R4 bug).
    #pragma unroll
    for (int i = TROWS + 3; i >= 4; i--) a[i] = o4 ? a[i - 4] : a[i];
    #pragma unroll
    for (int i = TROWS + 3; i >= 2; i--) a[i] = o2 ? a[i - 2] : a[i];
    #pragma unroll
    for (int i = TROWS + 3; i >= 1; i--) a[i] = o1 ? a[i - 1] : a[i];

    // ---- Store output rows [P, P+20), coalesced across the warp ----
    float* __restrict__ op = out + ((size_t)b * LROWS + P) * DCOLS + c;
    #pragma unroll
    for (int d = 0; d < TROWS; d++) op[d * DCOLS] = a[d + 4];
}

extern "C" void kernel_launch(void* const* d_in, const int* in_sizes, int n_in,
                              void* d_out, int out_size) {
    const float* v = (const float*)d_in[2];   // inputs: q (unused), k (unused), v
    float* out     = (float*)d_out;

    dim3 grid((LROWS / TROWS) * 2, 8);        // 400 x 8 = 3200 blocks, 256 thr
    swd_reg_kernel<<<grid, NTHREADS>>>(v, out);
}